// round 9
// baseline (speedup 1.0000x reference)
#include <cuda_runtime.h>
#include <cstdint>

#define N_NODES 100000
#define N_EDGES 1600000
#define F_HID 128
#define F_OUT 64
#define BN_EPS 1e-5f
#define SCAN_BLOCKS 98            // 98 * 1024 = 100352 >= N_NODES

// ---------------- device-global scratch (no allocations allowed) ----------------
__device__ __align__(16) float g_nout[N_NODES];
__device__ __align__(16) float g_nin[N_NODES];
__device__ __align__(16) float g_h1[(size_t)N_NODES * F_HID];
__device__ __align__(16) float g_h2[(size_t)N_NODES * F_HID];
__device__ __align__(16) int2  g_csr_pack[N_EDGES];             // {src, nout_bits} by dst
__device__ __align__(16) int   g_row_ptr[N_NODES + 1];
__device__ __align__(16) int   g_cursor[N_NODES];
__device__ __align__(16) int   g_deg_out[N_NODES];
__device__ __align__(16) int   g_deg_in[N_NODES];
__device__ __align__(16) int   g_partial[128];
__device__ __align__(16) float g_sum[F_HID];
__device__ __align__(16) float g_sumsq[F_HID];
__device__ __align__(16) float g_bna[F_HID];
__device__ __align__(16) float g_bnb[F_HID];
__device__ int g_idx_is64;
// precomputed tf32 hi/lo splits of W, transposed [n][k], row stride 133
__device__ __align__(16) uint32_t g_w1h[128 * 133];
__device__ __align__(16) uint32_t g_w1l[128 * 133];
__device__ __align__(16) uint32_t g_w2h[128 * 133];
__device__ __align__(16) uint32_t g_w2l[128 * 133];
__device__ __align__(16) uint32_t g_w3h[64 * 133];
__device__ __align__(16) uint32_t g_w3l[64 * 133];

// ---------------- tf32 helpers ----------------
__device__ __forceinline__ uint32_t f2tf(float v) {
    uint32_t r;
    asm("cvt.rna.tf32.f32 %0, %1;" : "=r"(r) : "f"(v));
    return r;
}

__device__ __forceinline__ void mma_tf32(float* c, const uint32_t* a,
                                         uint32_t b0, uint32_t b1) {
    asm volatile(
        "mma.sync.aligned.m16n8k8.row.col.f32.tf32.tf32.f32 "
        "{%0,%1,%2,%3}, {%4,%5,%6,%7}, {%8,%9}, {%0,%1,%2,%3};"
        : "+f"(c[0]), "+f"(c[1]), "+f"(c[2]), "+f"(c[3])
        : "r"(a[0]), "r"(a[1]), "r"(a[2]), "r"(a[3]), "r"(b0), "r"(b1));
}

__device__ __forceinline__ float4 bn_relu4(float4 v, float4 a, float4 c) {
    v.x = fmaxf(fmaf(v.x, a.x, c.x), 0.f);
    v.y = fmaxf(fmaf(v.y, a.y, c.y), 0.f);
    v.z = fmaxf(fmaf(v.z, a.z, c.z), 0.f);
    v.w = fmaxf(fmaf(v.w, a.w, c.w), 0.f);
    return v;
}

// ---------------- dtype detection ----------------
__global__ void detect_kernel(const int* __restrict__ srcbuf) {
    if (threadIdx.x == 0) {
        int all_zero = 1;
        #pragma unroll 1
        for (int k = 0; k < 64; k++) {
            if (srcbuf[2 * k + 1] != 0) { all_zero = 0; break; }
        }
        g_idx_is64 = all_zero;
    }
}

// ---------------- precompute W tf32 splits (transposed, stride 133) ----------------
__global__ void prep_w_kernel(const float* __restrict__ W1,
                              const float* __restrict__ W2,
                              const float* __restrict__ W3) {
    int i = blockIdx.x * blockDim.x + threadIdx.x;   // 16384 threads
    if (i < 128 * 128) {
        int k = i >> 7, n = i & 127;
        float w = W1[i];
        uint32_t h = f2tf(w);
        g_w1h[n * 133 + k] = h;
        g_w1l[n * 133 + k] = f2tf(w - __uint_as_float(h));
        w = W2[i];
        h = f2tf(w);
        g_w2h[n * 133 + k] = h;
        g_w2l[n * 133 + k] = f2tf(w - __uint_as_float(h));
    }
    if (i < 128 * 64) {
        int k = i >> 6, n = i & 63;
        float w = W3[i];
        uint32_t h = f2tf(w);
        g_w3h[n * 133 + k] = h;
        g_w3l[n * 133 + k] = f2tf(w - __uint_as_float(h));
    }
}

// ---------------- degree histogram ----------------
__global__ void degree_kernel(const int* __restrict__ sbuf,
                              const int* __restrict__ dbuf) {
    int e = blockIdx.x * blockDim.x + threadIdx.x;
    if (e < N_EDGES) {
        int is64 = g_idx_is64;
        int s = is64 ? ((const int2*)sbuf)[e].x : sbuf[e];
        int d = is64 ? ((const int2*)dbuf)[e].x : dbuf[e];
        atomicAdd(&g_deg_out[s], 1);
        atomicAdd(&g_deg_in[d], 1);
    }
}

// ---------------- scan pass A ----------------
__global__ __launch_bounds__(1024) void scanA_kernel() {
    __shared__ int wsum[32];
    int tid = threadIdx.x, lane = tid & 31, wid = tid >> 5;
    int i = blockIdx.x * 1024 + tid;
    int v = (i < N_NODES) ? g_deg_in[i] : 0;
    int s = v;
    #pragma unroll
    for (int off = 16; off > 0; off >>= 1)
        s += __shfl_down_sync(0xffffffffu, s, off);
    if (lane == 0) wsum[wid] = s;
    __syncthreads();
    if (wid == 0) {
        int t = wsum[lane];
        #pragma unroll
        for (int off = 16; off > 0; off >>= 1)
            t += __shfl_down_sync(0xffffffffu, t, off);
        if (lane == 0) g_partial[blockIdx.x] = t;
    }
}

// ---------------- scan pass B: offsets + local scan + norms ----------------
__global__ __launch_bounds__(1024) void scanB_kernel() {
    __shared__ int wsum[32];
    __shared__ int blockOffset;
    int tid = threadIdx.x, lane = tid & 31, wid = tid >> 5;

    if (wid == 0) {
        int acc = 0;
        for (int j = lane; j < blockIdx.x; j += 32) acc += g_partial[j];
        #pragma unroll
        for (int off = 16; off > 0; off >>= 1)
            acc += __shfl_down_sync(0xffffffffu, acc, off);
        if (lane == 0) blockOffset = acc;
    }

    int i = blockIdx.x * 1024 + tid;
    int v = (i < N_NODES) ? g_deg_in[i] : 0;
    int incl = v;
    #pragma unroll
    for (int off = 1; off < 32; off <<= 1) {
        int t = __shfl_up_sync(0xffffffffu, incl, off);
        if (lane >= off) incl += t;
    }
    if (lane == 31) wsum[wid] = incl;
    __syncthreads();
    if (wid == 0) {
        int wv = wsum[lane];
        int winc = wv;
        #pragma unroll
        for (int off = 1; off < 32; off <<= 1) {
            int t = __shfl_up_sync(0xffffffffu, winc, off);
            if (lane >= off) winc += t;
        }
        wsum[lane] = winc - wv;
    }
    __syncthreads();
    int excl = blockOffset + wsum[wid] + incl - v;
    if (i < N_NODES) {
        g_row_ptr[i] = excl;
        g_cursor[i] = excl;
        g_nout[i] = rsqrtf(fmaxf((float)g_deg_out[i], 1.f));
        g_nin[i]  = rsqrtf(fmaxf((float)v, 1.f));
        if (i == N_NODES - 1) g_row_ptr[N_NODES] = excl + v;
    }
}

// ---------------- bucket fill with packed payload {src, nout(src)} ----------------
__global__ void fill_csr_kernel(const int* __restrict__ sbuf,
                                const int* __restrict__ dbuf) {
    int e = blockIdx.x * blockDim.x + threadIdx.x;
    if (e < N_EDGES) {
        int is64 = g_idx_is64;
        int s = is64 ? ((const int2*)sbuf)[e].x : sbuf[e];
        int d = is64 ? ((const int2*)dbuf)[e].x : dbuf[e];
        int pos = atomicAdd(&g_cursor[d], 1);
        g_csr_pack[pos] = make_int2(s, __float_as_int(g_nout[s]));
    }
}

// ---------------- fused CSR-gather + TF32 mma GEMM, 64-row tile, 256 thr ----------------
// smem: As 64x132 fl | Wh 128x133 u32 (precomputed hi) | redS/redQ 4x128 fl
// Wl read from global through L1 (68 KB, L1-resident).
template<int LAYER>
__global__ __launch_bounds__(256)
void fused_conv_kernel(const float* __restrict__ x,
                       const uint32_t* __restrict__ Wh_g,
                       const uint32_t* __restrict__ Wl_g,
                       const float* __restrict__ bias,
                       float* __restrict__ out) {
    extern __shared__ float smem[];
    float*     As_f = smem;                          // 64*132
    float4*    As4  = (float4*)smem;                 // rows stride 33 float4
    uint32_t*  Wh   = (uint32_t*)(smem + 64 * 132);  // 128*133
    float*     redS = (float*)(Wh + 128 * 133);      // 4*128
    float*     redQ = redS + 512;                    // 4*128

    int tid = threadIdx.x;
    int lane = tid & 31;
    int wid = tid >> 5;
    int rowBase = blockIdx.x * 64;
    const float4* x4 = (const float4*)x;

    // stage W-hi (straight copy; transposed layout precomputed)
    for (int i = tid; i < 128 * 133; i += 256)
        Wh[i] = Wh_g[i];

    float4 a4 = make_float4(0.f, 0.f, 0.f, 0.f);
    float4 c4 = make_float4(0.f, 0.f, 0.f, 0.f);
    if (LAYER == 2) {
        a4 = ((const float4*)g_bna)[lane];
        c4 = ((const float4*)g_bnb)[lane];
    }

    // gather phase: dual-row per warp (rows r0, r0+8), unroll-4 each
    for (int r0 = wid; r0 < 64; r0 += 16) {
        int rA = r0, rB = r0 + 8;
        int gA = rowBase + rA, gB = rowBase + rB;
        int jA = 0, eA = 0, jB = 0, eB = 0;
        if (gA < N_NODES) { jA = g_row_ptr[gA]; eA = g_row_ptr[gA + 1]; }
        if (gB < N_NODES) { jB = g_row_ptr[gB]; eB = g_row_ptr[gB + 1]; }
        float4 accA = make_float4(0.f, 0.f, 0.f, 0.f);
        float4 accB = make_float4(0.f, 0.f, 0.f, 0.f);

        while (jA + 4 <= eA && jB + 4 <= eB) {
            int2 pA[4], pB[4];
            #pragma unroll
            for (int u = 0; u < 4; u++) { pA[u] = g_csr_pack[jA + u]; pB[u] = g_csr_pack[jB + u]; }
            float4 vA[4], vB[4];
            #pragma unroll
            for (int u = 0; u < 4; u++) {
                vA[u] = x4[(size_t)pA[u].x * 32 + lane];
                vB[u] = x4[(size_t)pB[u].x * 32 + lane];
            }
            #pragma unroll
            for (int u = 0; u < 4; u++) {
                float nA = __int_as_float(pA[u].y);
                float nB = __int_as_float(pB[u].y);
                float4 wA = (LAYER == 2) ? bn_relu4(vA[u], a4, c4) : vA[u];
                float4 wB = (LAYER == 2) ? bn_relu4(vB[u], a4, c4) : vB[u];
                accA.x = fmaf(wA.x, nA, accA.x); accA.y = fmaf(wA.y, nA, accA.y);
                accA.z = fmaf(wA.z, nA, accA.z); accA.w = fmaf(wA.w, nA, accA.w);
                accB.x = fmaf(wB.x, nB, accB.x); accB.y = fmaf(wB.y, nB, accB.y);
                accB.z = fmaf(wB.z, nB, accB.z); accB.w = fmaf(wB.w, nB, accB.w);
            }
            jA += 4; jB += 4;
        }
        while (jA + 4 <= eA) {
            int2 p[4];
            #pragma unroll
            for (int u = 0; u < 4; u++) p[u] = g_csr_pack[jA + u];
            float4 v[4];
            #pragma unroll
            for (int u = 0; u < 4; u++) v[u] = x4[(size_t)p[u].x * 32 + lane];
            #pragma unroll
            for (int u = 0; u < 4; u++) {
                float n = __int_as_float(p[u].y);
                float4 w = (LAYER == 2) ? bn_relu4(v[u], a4, c4) : v[u];
                accA.x = fmaf(w.x, n, accA.x); accA.y = fmaf(w.y, n, accA.y);
                accA.z = fmaf(w.z, n, accA.z); accA.w = fmaf(w.w, n, accA.w);
            }
            jA += 4;
        }
        for (; jA < eA; jA++) {
            int2 p = g_csr_pack[jA];
            float n = __int_as_float(p.y);
            float4 v = x4[(size_t)p.x * 32 + lane];
            if (LAYER == 2) v = bn_relu4(v, a4, c4);
            accA.x = fmaf(v.x, n, accA.x); accA.y = fmaf(v.y, n, accA.y);
            accA.z = fmaf(v.z, n, accA.z); accA.w = fmaf(v.w, n, accA.w);
        }
        while (jB + 4 <= eB) {
            int2 p[4];
            #pragma unroll
            for (int u = 0; u < 4; u++) p[u] = g_csr_pack[jB + u];
            float4 v[4];
            #pragma unroll
            for (int u = 0; u < 4; u++) v[u] = x4[(size_t)p[u].x * 32 + lane];
            #pragma unroll
            for (int u = 0; u < 4; u++) {
                float n = __int_as_float(p[u].y);
                float4 w = (LAYER == 2) ? bn_relu4(v[u], a4, c4) : v[u];
                accB.x = fmaf(w.x, n, accB.x); accB.y = fmaf(w.y, n, accB.y);
                accB.z = fmaf(w.z, n, accB.z); accB.w = fmaf(w.w, n, accB.w);
            }
            jB += 4;
        }
        for (; jB < eB; jB++) {
            int2 p = g_csr_pack[jB];
            float n = __int_as_float(p.y);
            float4 v = x4[(size_t)p.x * 32 + lane];
            if (LAYER == 2) v = bn_relu4(v, a4, c4);
            accB.x = fmaf(v.x, n, accB.x); accB.y = fmaf(v.y, n, accB.y);
            accB.z = fmaf(v.z, n, accB.z); accB.w = fmaf(v.w, n, accB.w);
        }

        if (gA < N_NODES) {
            float ni = g_nin[gA];
            accA.x *= ni; accA.y *= ni; accA.z *= ni; accA.w *= ni;
        }
        if (gB < N_NODES) {
            float ni = g_nin[gB];
            accB.x *= ni; accB.y *= ni; accB.z *= ni; accB.w *= ni;
        }
        As4[rA * 33 + lane] = accA;
        As4[rB * 33 + lane] = accB;
    }
    __syncthreads();

    // mma phase: warp (warp_m 0..3, wn 0..1) computes m16 x n64, K=128
    int warp_m = wid & 3;
    int wn = wid >> 2;
    int qr = lane >> 2;       // 0..7
    int rr = lane & 3;        // 0..3
    int m0 = warp_m * 16 + qr;

    float c[8][4];
    #pragma unroll
    for (int nt = 0; nt < 8; nt++)
        #pragma unroll
        for (int q = 0; q < 4; q++) c[nt][q] = 0.f;

    #pragma unroll 2
    for (int ks = 0; ks < 16; ks++) {
        int k0 = ks * 8;
        float av0 = As_f[m0 * 132 + k0 + rr];
        float av1 = As_f[(m0 + 8) * 132 + k0 + rr];
        float av2 = As_f[m0 * 132 + k0 + 4 + rr];
        float av3 = As_f[(m0 + 8) * 132 + k0 + 4 + rr];
        uint32_t ah[4], al[4];
        ah[0] = f2tf(av0); al[0] = f2tf(av0 - __uint_as_float(ah[0]));
        ah[1] = f2tf(av1); al[1] = f2tf(av1 - __uint_as_float(ah[1]));
        ah[2] = f2tf(av2); al[2] = f2tf(av2 - __uint_as_float(ah[2]));
        ah[3] = f2tf(av3); al[3] = f2tf(av3 - __uint_as_float(ah[3]));
        #pragma unroll
        for (int nt = 0; nt < 8; nt++) {
            int nb = (wn * 64 + nt * 8 + qr) * 133 + k0 + rr;
            uint32_t bh0 = Wh[nb], bh1 = Wh[nb + 4];
            uint32_t bl0 = __ldg(&Wl_g[nb]);
            uint32_t bl1 = __ldg(&Wl_g[nb + 4]);
            mma_tf32(c[nt], ah, bh0, bh1);   // hi*hi
            mma_tf32(c[nt], al, bh0, bh1);   // lo*hi
            mma_tf32(c[nt], ah, bl0, bl1);   // hi*lo
        }
    }

    // epilogue: bias, store, BN stats
    int g0 = rowBase + m0;
    int g1 = g0 + 8;
    bool v0r = (g0 < N_NODES), v1r = (g1 < N_NODES);
    #pragma unroll
    for (int nt = 0; nt < 8; nt++) {
        int col = wn * 64 + nt * 8 + 2 * rr;
        float b0 = bias[col], b1 = bias[col + 1];
        float h00 = c[nt][0] + b0, h01 = c[nt][1] + b1;
        float h10 = c[nt][2] + b0, h11 = c[nt][3] + b1;
        if (v0r) *(float2*)&out[(size_t)g0 * 128 + col] = make_float2(h00, h01);
        if (v1r) *(float2*)&out[(size_t)g1 * 128 + col] = make_float2(h10, h11);
        float sA = (v0r ? h00 : 0.f) + (v1r ? h10 : 0.f);
        float sB = (v0r ? h01 : 0.f) + (v1r ? h11 : 0.f);
        float qA = (v0r ? h00 * h00 : 0.f) + (v1r ? h10 * h10 : 0.f);
        float qB = (v0r ? h01 * h01 : 0.f) + (v1r ? h11 * h11 : 0.f);
        #pragma unroll
        for (int off = 16; off >= 4; off >>= 1) {
            sA += __shfl_down_sync(0xffffffffu, sA, off);
            sB += __shfl_down_sync(0xffffffffu, sB, off);
            qA += __shfl_down_sync(0xffffffffu, qA, off);
            qB += __shfl_down_sync(0xffffffffu, qB, off);
        }
        if (lane < 4) {
            *(float2*)&redS[warp_m * 128 + col] = make_float2(sA, sB);
            *(float2*)&redQ[warp_m * 128 + col] = make_float2(qA, qB);
        }
    }
    __syncthreads();
    if (tid < 128) {
        float s = redS[tid] + redS[128 + tid] + redS[256 + tid] + redS[384 + tid];
        float q = redQ[tid] + redQ[128 + tid] + redQ[256 + tid] + redQ[384 + tid];
        atomicAdd(&g_sum[tid], s);
        atomicAdd(&g_sumsq[tid], q);
    }
}

// ---------------- layer-3 mma GEMM: y = relu(bn2(h2)) @ W3 * n_out ----------------
__global__ __launch_bounds__(256)
void mma_gemm64_kernel(const float* __restrict__ A,
                       float* __restrict__ out) {
    extern __shared__ float smem[];
    float*     As_f = smem;                          // 64*132
    float4*    As4  = (float4*)smem;
    uint32_t*  Wh   = (uint32_t*)(smem + 64 * 132);  // 64*133
    uint32_t*  Wl   = Wh + 64 * 133;

    int tid = threadIdx.x;
    int rowBase = blockIdx.x * 64;

    for (int i = tid; i < 64 * 133; i += 256) {
        Wh[i] = g_w3h[i];
        Wl[i] = g_w3l[i];
    }

    #pragma unroll
    for (int i = 0; i < 8; i++) {
        int slot = tid + i * 256;
        int lrow = slot >> 5;
        int kk = slot & 31;
        int grow = rowBase + lrow;
        float4 v = make_float4(0.f, 0.f, 0.f, 0.f);
        if (grow < N_NODES) {
            v = ((const float4*)A)[(size_t)grow * 32 + kk];
            float4 a4 = ((const float4*)g_bna)[kk];
            float4 b4 = ((const float4*)g_bnb)[kk];
            v = bn_relu4(v, a4, b4);
        }
        As4[lrow * 33 + kk] = v;
    }
    __syncthreads();

    int lane = tid & 31;
    int wid = tid >> 5;
    int warp_m = wid & 3;
    int wn = wid >> 2;
    int qr = lane >> 2;
    int rr = lane & 3;
    int m0 = warp_m * 16 + qr;

    float c[4][4];
    #pragma unroll
    for (int nt = 0; nt < 4; nt++)
        #pragma unroll
        for (int q = 0; q < 4; q++) c[nt][q] = 0.f;

    #pragma unroll 2
    for (int ks = 0; ks < 16; ks++) {
        int k0 = ks * 8;
        float av0 = As_f[m0 * 132 + k0 + rr];
        float av1 = As_f[(m0 + 8) * 132 + k0 + rr];
        float av2 = As_f[m0 * 132 + k0 + 4 + rr];
        float av3 = As_f[(m0 + 8) * 132 + k0 + 4 + rr];
        uint32_t ah[4], al[4];
        ah[0] = f2tf(av0); al[0] = f2tf(av0 - __uint_as_float(ah[0]));
        ah[1] = f2tf(av1); al[1] = f2tf(av1 - __uint_as_float(ah[1]));
        ah[2] = f2tf(av2); al[2] = f2tf(av2 - __uint_as_float(ah[2]));
        ah[3] = f2tf(av3); al[3] = f2tf(av3 - __uint_as_float(ah[3]));
        #pragma unroll
        for (int nt = 0; nt < 4; nt++) {
            int nb = (wn * 32 + nt * 8 + qr) * 133 + k0 + rr;
            uint32_t bh0 = Wh[nb], bh1 = Wh[nb + 4];
            uint32_t bl0 = Wl[nb], bl1 = Wl[nb + 4];
            mma_tf32(c[nt], ah, bh0, bh1);
            mma_tf32(c[nt], al, bh0, bh1);
            mma_tf32(c[nt], ah, bl0, bl1);
        }
    }

    int g0 = rowBase + m0;
    int g1 = g0 + 8;
    float s0 = (g0 < N_NODES) ? g_nout[g0] : 0.f;
    float s1 = (g1 < N_NODES) ? g_nout[g1] : 0.f;
    #pragma unroll
    for (int nt = 0; nt < 4; nt++) {
        int col = wn * 32 + nt * 8 + 2 * rr;
        if (g0 < N_NODES)
            *(float2*)&out[(size_t)g0 * 64 + col] =
                make_float2(c[nt][0] * s0, c[nt][1] * s0);
        if (g1 < N_NODES)
            *(float2*)&out[(size_t)g1 * 64 + col] =
                make_float2(c[nt][2] * s1, c[nt][3] * s1);
    }
}

// ---------------- BN finalize ----------------
__global__ void bn_finalize_kernel(const float* __restrict__ gamma,
                                   const float* __restrict__ beta) {
    int t = threadIdx.x;
    if (t < F_HID) {
        float mean = g_sum[t] / (float)N_NODES;
        float var = g_sumsq[t] / (float)N_NODES - mean * mean;
        float a = gamma[t] * rsqrtf(var + BN_EPS);
        g_bna[t] = a;
        g_bnb[t] = fmaf(-mean, a, beta[t]);
        g_sum[t] = 0.f;
        g_sumsq[t] = 0.f;
    }
}

// ---------------- final CSR gather (64 feats), dual-node per warp ----------------
__global__ void gather64_kernel(const float* __restrict__ y,
                                const float* __restrict__ b3,
                                float* __restrict__ out) {
    int w = (blockIdx.x * blockDim.x + threadIdx.x) >> 5;
    int lane = threadIdx.x & 31;
    int nA = 2 * w, nB = 2 * w + 1;
    if (nA >= N_NODES) return;
    const float2* y2 = (const float2*)y;

    int jA = g_row_ptr[nA], eA = g_row_ptr[nA + 1];
    int jB = 0, eB = 0;
    if (nB < N_NODES) { jB = g_row_ptr[nB]; eB = g_row_ptr[nB + 1]; }
    float2 accA = make_float2(0.f, 0.f);
    float2 accB = make_float2(0.f, 0.f);

    while (jA + 4 <= eA && jB + 4 <= eB) {
        int sA[4], sB[4];
        #pragma unroll
        for (int u = 0; u < 4; u++) { sA[u] = g_csr_pack[jA + u].x; sB[u] = g_csr_pack[jB + u].x; }
        float2 vA[4], vB[4];
        #pragma unroll
        for (int u = 0; u < 4; u++) {
            vA[u] = y2[(size_t)sA[u] * 32 + lane];
            vB[u] = y2[(size_t)sB[u] * 32 + lane];
        }
        #pragma unroll
        for (int u = 0; u < 4; u++) {
            accA.x += vA[u].x; accA.y += vA[u].y;
            accB.x += vB[u].x; accB.y += vB[u].y;
        }
        jA += 4; jB += 4;
    }
    for (; jA < eA; jA++) {
        float2 v = y2[(size_t)g_csr_pack[jA].x * 32 + lane];
        accA.x += v.x; accA.y += v.y;
    }
    for (; jB < eB; jB++) {
        float2 v = y2[(size_t)g_csr_pack[jB].x * 32 + lane];
        accB.x += v.x; accB.y += v.y;
    }

    float2 b = ((const float2*)b3)[lane];
    float niA = g_nin[nA];
    ((float2*)out)[(size_t)nA * 32 + lane] =
        make_float2(fmaf(accA.x, niA, b.x), fmaf(accA.y, niA, b.y));
    if (nB < N_NODES) {
        float niB = g_nin[nB];
        ((float2*)out)[(size_t)nB * 32 + lane] =
            make_float2(fmaf(accB.x, niB, b.x), fmaf(accB.y, niB, b.y));
    }
}

// ---------------- host launcher ----------------
extern "C" void kernel_launch(void* const* d_in, const int* in_sizes, int n_in,
                              void* d_out, int out_size) {
    const float* features = (const float*)d_in[0];
    const int*   srcbuf   = (const int*)d_in[1];
    const int*   dstbuf   = (const int*)d_in[2];
    const float* W1  = (const float*)d_in[3];
    const float* b1  = (const float*)d_in[4];
    const float* ga1 = (const float*)d_in[5];
    const float* be1 = (const float*)d_in[6];
    const float* W2  = (const float*)d_in[7];
    const float* b2  = (const float*)d_in[8];
    const float* ga2 = (const float*)d_in[9];
    const float* be2 = (const float*)d_in[10];
    const float* W3  = (const float*)d_in[11];
    const float* b3  = (const float*)d_in[12];
    float* out = (float*)d_out;

    void* p;
    cudaGetSymbolAddress(&p, g_h1);
    float* p_h1 = (float*)p;
    cudaGetSymbolAddress(&p, g_h2);
    float* p_h2 = (float*)p;
    void *p_do, *p_di, *p_sum, *p_sq;
    cudaGetSymbolAddress(&p_do, g_deg_out);
    cudaGetSymbolAddress(&p_di, g_deg_in);
    cudaGetSymbolAddress(&p_sum, g_sum);
    cudaGetSymbolAddress(&p_sq, g_sumsq);
    void *p_w1h, *p_w1l, *p_w2h, *p_w2l;
    cudaGetSymbolAddress(&p_w1h, g_w1h);
    cudaGetSymbolAddress(&p_w1l, g_w1l);
    cudaGetSymbolAddress(&p_w2h, g_w2h);
    cudaGetSymbolAddress(&p_w2l, g_w2l);

    constexpr int SM_CONV = 64 * 132 * 4 + 128 * 133 * 4 + 2 * 512 * 4;   // 105984
    constexpr int SM_G64  = 64 * 132 * 4 + 2 * 64 * 133 * 4;              // 101888

    cudaFuncSetAttribute(fused_conv_kernel<1>,
                         cudaFuncAttributeMaxDynamicSharedMemorySize, SM_CONV);
    cudaFuncSetAttribute(fused_conv_kernel<2>,
                         cudaFuncAttributeMaxDynamicSharedMemorySize, SM_CONV);
    cudaFuncSetAttribute(mma_gemm64_kernel,
                         cudaFuncAttributeMaxDynamicSharedMemorySize, SM_G64);

    int eblk = (N_EDGES + 255) / 256;
    int gblk = (N_NODES + 63) / 64;       // 1563

    // graph preprocessing
    cudaMemsetAsync(p_do, 0, N_NODES * sizeof(int));
    cudaMemsetAsync(p_di, 0, N_NODES * sizeof(int));
    cudaMemsetAsync(p_sum, 0, F_HID * sizeof(float));
    cudaMemsetAsync(p_sq, 0, F_HID * sizeof(float));
    detect_kernel<<<1, 32>>>(srcbuf);
    prep_w_kernel<<<64, 256>>>(W1, W2, W3);
    degree_kernel<<<eblk, 256>>>(srcbuf, dstbuf);
    scanA_kernel<<<SCAN_BLOCKS, 1024>>>();
    scanB_kernel<<<SCAN_BLOCKS, 1024>>>();
    fill_csr_kernel<<<eblk, 256>>>(srcbuf, dstbuf);

    // ---- layer 1 ----
    fused_conv_kernel<1><<<gblk, 256, SM_CONV>>>(features, (const uint32_t*)p_w1h,
                                                 (const uint32_t*)p_w1l, b1, p_h1);
    bn_finalize_kernel<<<1, 128>>>(ga1, be1);

    // ---- layer 2 ----
    fused_conv_kernel<2><<<gblk, 256, SM_CONV>>>(p_h1, (const uint32_t*)p_w2h,
                                                 (const uint32_t*)p_w2l, b2, p_h2);
    bn_finalize_kernel<<<1, 128>>>(ga2, be2);

    // ---- layer 3: GEMM first (aggregation commutes with W3), then CSR gather ----
    mma_gemm64_kernel<<<gblk, 256, SM_G64>>>(p_h2, p_h1);
    gather64_kernel<<<(N_NODES / 2 + 7) / 8, 256>>>(p_h1, b3, out);
}

// round 10
// speedup vs baseline: 1.1773x; 1.1773x over previous
#include <cuda_runtime.h>
#include <cstdint>

#define N_NODES 100000
#define N_EDGES 1600000
#define F_HID 128
#define F_OUT 64
#define BN_EPS 1e-5f
#define SCAN_BLOCKS 98            // 98 * 1024 = 100352 >= N_NODES
#define PERSIST_BLOCKS 296        // 2 blocks/SM x 148 SMs
#define N_TILES ((N_NODES + 63) / 64)

// ---------------- device-global scratch (no allocations allowed) ----------------
__device__ __align__(16) float g_nout[N_NODES];
__device__ __align__(16) float g_nin[N_NODES];
__device__ __align__(16) float g_h1[(size_t)N_NODES * F_HID];
__device__ __align__(16) float g_h2[(size_t)N_NODES * F_HID];
__device__ __align__(16) int2  g_csr_pack[N_EDGES];             // {src, nout_bits} by dst
__device__ __align__(16) int   g_row_ptr[N_NODES + 1];
__device__ __align__(16) int   g_cursor[N_NODES];
__device__ __align__(16) int   g_deg_out[N_NODES];
__device__ __align__(16) int   g_deg_in[N_NODES];
__device__ __align__(16) int   g_partial[128];
__device__ __align__(16) float g_sum[F_HID];
__device__ __align__(16) float g_sumsq[F_HID];
__device__ __align__(16) float g_bna[F_HID];
__device__ __align__(16) float g_bnb[F_HID];
__device__ int g_idx_is64;

// ---------------- tf32 helpers ----------------
__device__ __forceinline__ uint32_t f2tf(float v) {
    uint32_t r;
    asm("cvt.rna.tf32.f32 %0, %1;" : "=r"(r) : "f"(v));
    return r;
}

__device__ __forceinline__ void mma_tf32(float* c, const uint32_t* a,
                                         uint32_t b0, uint32_t b1) {
    asm volatile(
        "mma.sync.aligned.m16n8k8.row.col.f32.tf32.tf32.f32 "
        "{%0,%1,%2,%3}, {%4,%5,%6,%7}, {%8,%9}, {%0,%1,%2,%3};"
        : "+f"(c[0]), "+f"(c[1]), "+f"(c[2]), "+f"(c[3])
        : "r"(a[0]), "r"(a[1]), "r"(a[2]), "r"(a[3]), "r"(b0), "r"(b1));
}

__device__ __forceinline__ float4 bn_relu4(float4 v, float4 a, float4 c) {
    v.x = fmaxf(fmaf(v.x, a.x, c.x), 0.f);
    v.y = fmaxf(fmaf(v.y, a.y, c.y), 0.f);
    v.z = fmaxf(fmaf(v.z, a.z, c.z), 0.f);
    v.w = fmaxf(fmaf(v.w, a.w, c.w), 0.f);
    return v;
}

// ---------------- dtype detection ----------------
__global__ void detect_kernel(const int* __restrict__ srcbuf) {
    if (threadIdx.x == 0) {
        int all_zero = 1;
        #pragma unroll 1
        for (int k = 0; k < 64; k++) {
            if (srcbuf[2 * k + 1] != 0) { all_zero = 0; break; }
        }
        g_idx_is64 = all_zero;
    }
}

// ---------------- degree histogram ----------------
__global__ void degree_kernel(const int* __restrict__ sbuf,
                              const int* __restrict__ dbuf) {
    int e = blockIdx.x * blockDim.x + threadIdx.x;
    if (e < N_EDGES) {
        int is64 = g_idx_is64;
        int s = is64 ? ((const int2*)sbuf)[e].x : sbuf[e];
        int d = is64 ? ((const int2*)dbuf)[e].x : dbuf[e];
        atomicAdd(&g_deg_out[s], 1);
        atomicAdd(&g_deg_in[d], 1);
    }
}

// ---------------- scan pass A ----------------
__global__ __launch_bounds__(1024) void scanA_kernel() {
    __shared__ int wsum[32];
    int tid = threadIdx.x, lane = tid & 31, wid = tid >> 5;
    int i = blockIdx.x * 1024 + tid;
    int v = (i < N_NODES) ? g_deg_in[i] : 0;
    int s = v;
    #pragma unroll
    for (int off = 16; off > 0; off >>= 1)
        s += __shfl_down_sync(0xffffffffu, s, off);
    if (lane == 0) wsum[wid] = s;
    __syncthreads();
    if (wid == 0) {
        int t = wsum[lane];
        #pragma unroll
        for (int off = 16; off > 0; off >>= 1)
            t += __shfl_down_sync(0xffffffffu, t, off);
        if (lane == 0) g_partial[blockIdx.x] = t;
    }
}

// ---------------- scan pass B: offsets + local scan + norms ----------------
__global__ __launch_bounds__(1024) void scanB_kernel() {
    __shared__ int wsum[32];
    __shared__ int blockOffset;
    int tid = threadIdx.x, lane = tid & 31, wid = tid >> 5;

    if (wid == 0) {
        int acc = 0;
        for (int j = lane; j < blockIdx.x; j += 32) acc += g_partial[j];
        #pragma unroll
        for (int off = 16; off > 0; off >>= 1)
            acc += __shfl_down_sync(0xffffffffu, acc, off);
        if (lane == 0) blockOffset = acc;
    }

    int i = blockIdx.x * 1024 + tid;
    int v = (i < N_NODES) ? g_deg_in[i] : 0;
    int incl = v;
    #pragma unroll
    for (int off = 1; off < 32; off <<= 1) {
        int t = __shfl_up_sync(0xffffffffu, incl, off);
        if (lane >= off) incl += t;
    }
    if (lane == 31) wsum[wid] = incl;
    __syncthreads();
    if (wid == 0) {
        int wv = wsum[lane];
        int winc = wv;
        #pragma unroll
        for (int off = 1; off < 32; off <<= 1) {
            int t = __shfl_up_sync(0xffffffffu, winc, off);
            if (lane >= off) winc += t;
        }
        wsum[lane] = winc - wv;
    }
    __syncthreads();
    int excl = blockOffset + wsum[wid] + incl - v;
    if (i < N_NODES) {
        g_row_ptr[i] = excl;
        g_cursor[i] = excl;
        g_nout[i] = rsqrtf(fmaxf((float)g_deg_out[i], 1.f));
        g_nin[i]  = rsqrtf(fmaxf((float)v, 1.f));
        if (i == N_NODES - 1) g_row_ptr[N_NODES] = excl + v;
    }
}

// ---------------- bucket fill with packed payload {src, nout(src)} ----------------
__global__ void fill_csr_kernel(const int* __restrict__ sbuf,
                                const int* __restrict__ dbuf) {
    int e = blockIdx.x * blockDim.x + threadIdx.x;
    if (e < N_EDGES) {
        int is64 = g_idx_is64;
        int s = is64 ? ((const int2*)sbuf)[e].x : sbuf[e];
        int d = is64 ? ((const int2*)dbuf)[e].x : dbuf[e];
        int pos = atomicAdd(&g_cursor[d], 1);
        g_csr_pack[pos] = make_int2(s, __float_as_int(g_nout[s]));
    }
}

// ---------------- fused CSR-gather + TF32 mma GEMM (R7 structure, persistent tiles) ----
// smem: As 64x132 fl | Wt 128x133 fl (transposed W) | redS/redQ 4x128 fl
// Each block stages W ONCE, then loops over row tiles.
template<int LAYER>
__global__ __launch_bounds__(256)
void fused_conv_kernel(const float* __restrict__ x,
                       const float* __restrict__ W,
                       const float* __restrict__ bias,
                       float* __restrict__ out) {
    extern __shared__ float smem[];
    float*  As_f = smem;                    // 64*132
    float4* As4  = (float4*)smem;           // rows stride 33 float4
    float*  Wt   = smem + 64 * 132;         // 128*133 (transposed W)
    float*  redS = Wt + 128 * 133;          // 4*128
    float*  redQ = redS + 512;              // 4*128

    int tid = threadIdx.x;
    int lane = tid & 31;
    int wid = tid >> 5;
    const float4* x4 = (const float4*)x;

    // stage W transposed ONCE: Wt[n*133 + k] = W[k*128 + n]
    for (int i = tid; i < 128 * 128; i += 256) {
        int k = i >> 7, n = i & 127;
        Wt[n * 133 + k] = W[i];
    }

    float4 a4 = make_float4(0.f, 0.f, 0.f, 0.f);
    float4 c4 = make_float4(0.f, 0.f, 0.f, 0.f);
    if (LAYER == 2) {
        a4 = ((const float4*)g_bna)[lane];
        c4 = ((const float4*)g_bnb)[lane];
    }

    // mma-phase thread mapping (loop-invariant)
    int warp_m = wid & 3;
    int wn = wid >> 2;
    int qr = lane >> 2;       // 0..7
    int rr = lane & 3;        // 0..3
    int m0 = warp_m * 16 + qr;

    for (int tile = blockIdx.x; tile < N_TILES; tile += gridDim.x) {
        int rowBase = tile * 64;
        __syncthreads();   // W staged (first iter) / prior tile fully done

        // ---- gather phase: dual-row per warp (rows r0, r0+8), unroll-4 each ----
        for (int r0 = wid; r0 < 64; r0 += 16) {
            int rA = r0, rB = r0 + 8;
            int gA = rowBase + rA, gB = rowBase + rB;
            int jA = 0, eA = 0, jB = 0, eB = 0;
            if (gA < N_NODES) { jA = g_row_ptr[gA]; eA = g_row_ptr[gA + 1]; }
            if (gB < N_NODES) { jB = g_row_ptr[gB]; eB = g_row_ptr[gB + 1]; }
            float4 accA = make_float4(0.f, 0.f, 0.f, 0.f);
            float4 accB = make_float4(0.f, 0.f, 0.f, 0.f);

            while (jA + 4 <= eA && jB + 4 <= eB) {
                int2 pA[4], pB[4];
                #pragma unroll
                for (int u = 0; u < 4; u++) { pA[u] = g_csr_pack[jA + u]; pB[u] = g_csr_pack[jB + u]; }
                float4 vA[4], vB[4];
                #pragma unroll
                for (int u = 0; u < 4; u++) {
                    vA[u] = x4[(size_t)pA[u].x * 32 + lane];
                    vB[u] = x4[(size_t)pB[u].x * 32 + lane];
                }
                #pragma unroll
                for (int u = 0; u < 4; u++) {
                    float nA = __int_as_float(pA[u].y);
                    float nB = __int_as_float(pB[u].y);
                    float4 wA = (LAYER == 2) ? bn_relu4(vA[u], a4, c4) : vA[u];
                    float4 wB = (LAYER == 2) ? bn_relu4(vB[u], a4, c4) : vB[u];
                    accA.x = fmaf(wA.x, nA, accA.x); accA.y = fmaf(wA.y, nA, accA.y);
                    accA.z = fmaf(wA.z, nA, accA.z); accA.w = fmaf(wA.w, nA, accA.w);
                    accB.x = fmaf(wB.x, nB, accB.x); accB.y = fmaf(wB.y, nB, accB.y);
                    accB.z = fmaf(wB.z, nB, accB.z); accB.w = fmaf(wB.w, nB, accB.w);
                }
                jA += 4; jB += 4;
            }
            while (jA + 4 <= eA) {
                int2 p[4];
                #pragma unroll
                for (int u = 0; u < 4; u++) p[u] = g_csr_pack[jA + u];
                float4 v[4];
                #pragma unroll
                for (int u = 0; u < 4; u++) v[u] = x4[(size_t)p[u].x * 32 + lane];
                #pragma unroll
                for (int u = 0; u < 4; u++) {
                    float n = __int_as_float(p[u].y);
                    float4 w = (LAYER == 2) ? bn_relu4(v[u], a4, c4) : v[u];
                    accA.x = fmaf(w.x, n, accA.x); accA.y = fmaf(w.y, n, accA.y);
                    accA.z = fmaf(w.z, n, accA.z); accA.w = fmaf(w.w, n, accA.w);
                }
                jA += 4;
            }
            for (; jA < eA; jA++) {
                int2 p = g_csr_pack[jA];
                float n = __int_as_float(p.y);
                float4 v = x4[(size_t)p.x * 32 + lane];
                if (LAYER == 2) v = bn_relu4(v, a4, c4);
                accA.x = fmaf(v.x, n, accA.x); accA.y = fmaf(v.y, n, accA.y);
                accA.z = fmaf(v.z, n, accA.z); accA.w = fmaf(v.w, n, accA.w);
            }
            while (jB + 4 <= eB) {
                int2 p[4];
                #pragma unroll
                for (int u = 0; u < 4; u++) p[u] = g_csr_pack[jB + u];
                float4 v[4];
                #pragma unroll
                for (int u = 0; u < 4; u++) v[u] = x4[(size_t)p[u].x * 32 + lane];
                #pragma unroll
                for (int u = 0; u < 4; u++) {
                    float n = __int_as_float(p[u].y);
                    float4 w = (LAYER == 2) ? bn_relu4(v[u], a4, c4) : v[u];
                    accB.x = fmaf(w.x, n, accB.x); accB.y = fmaf(w.y, n, accB.y);
                    accB.z = fmaf(w.z, n, accB.z); accB.w = fmaf(w.w, n, accB.w);
                }
                jB += 4;
            }
            for (; jB < eB; jB++) {
                int2 p = g_csr_pack[jB];
                float n = __int_as_float(p.y);
                float4 v = x4[(size_t)p.x * 32 + lane];
                if (LAYER == 2) v = bn_relu4(v, a4, c4);
                accB.x = fmaf(v.x, n, accB.x); accB.y = fmaf(v.y, n, accB.y);
                accB.z = fmaf(v.z, n, accB.z); accB.w = fmaf(v.w, n, accB.w);
            }

            if (gA < N_NODES) {
                float ni = g_nin[gA];
                accA.x *= ni; accA.y *= ni; accA.z *= ni; accA.w *= ni;
            }
            if (gB < N_NODES) {
                float ni = g_nin[gB];
                accB.x *= ni; accB.y *= ni; accB.z *= ni; accB.w *= ni;
            }
            As4[rA * 33 + lane] = accA;
            As4[rB * 33 + lane] = accB;
        }
        __syncthreads();

        // ---- mma phase: warp (warp_m, wn) computes m16 x n64, K=128 ----
        float c[8][4];
        #pragma unroll
        for (int nt = 0; nt < 8; nt++)
            #pragma unroll
            for (int q = 0; q < 4; q++) c[nt][q] = 0.f;

        #pragma unroll 2
        for (int ks = 0; ks < 16; ks++) {
            int k0 = ks * 8;
            float av0 = As_f[m0 * 132 + k0 + rr];
            float av1 = As_f[(m0 + 8) * 132 + k0 + rr];
            float av2 = As_f[m0 * 132 + k0 + 4 + rr];
            float av3 = As_f[(m0 + 8) * 132 + k0 + 4 + rr];
            uint32_t ah[4], al[4];
            ah[0] = f2tf(av0); al[0] = f2tf(av0 - __uint_as_float(ah[0]));
            ah[1] = f2tf(av1); al[1] = f2tf(av1 - __uint_as_float(ah[1]));
            ah[2] = f2tf(av2); al[2] = f2tf(av2 - __uint_as_float(ah[2]));
            ah[3] = f2tf(av3); al[3] = f2tf(av3 - __uint_as_float(ah[3]));
            #pragma unroll
            for (int nt = 0; nt < 8; nt++) {
                int nb = (wn * 64 + nt * 8 + qr) * 133 + k0 + rr;
                float b0 = Wt[nb];
                float b1 = Wt[nb + 4];
                uint32_t bh0 = f2tf(b0);
                uint32_t bh1 = f2tf(b1);
                uint32_t bl0 = __float_as_uint(b0 - __uint_as_float(bh0));
                uint32_t bl1 = __float_as_uint(b1 - __uint_as_float(bh1));
                mma_tf32(c[nt], ah, bh0, bh1);   // hi*hi
                mma_tf32(c[nt], al, bh0, bh1);   // lo*hi
                mma_tf32(c[nt], ah, bl0, bl1);   // hi*lo
            }
        }

        // ---- epilogue: bias, store, BN stats ----
        int g0 = rowBase + m0;
        int g1 = g0 + 8;
        bool v0r = (g0 < N_NODES), v1r = (g1 < N_NODES);
        #pragma unroll
        for (int nt = 0; nt < 8; nt++) {
            int col = wn * 64 + nt * 8 + 2 * rr;
            float b0 = bias[col], b1 = bias[col + 1];
            float h00 = c[nt][0] + b0, h01 = c[nt][1] + b1;
            float h10 = c[nt][2] + b0, h11 = c[nt][3] + b1;
            if (v0r) *(float2*)&out[(size_t)g0 * 128 + col] = make_float2(h00, h01);
            if (v1r) *(float2*)&out[(size_t)g1 * 128 + col] = make_float2(h10, h11);
            float sA = (v0r ? h00 : 0.f) + (v1r ? h10 : 0.f);
            float sB = (v0r ? h01 : 0.f) + (v1r ? h11 : 0.f);
            float qA = (v0r ? h00 * h00 : 0.f) + (v1r ? h10 * h10 : 0.f);
            float qB = (v0r ? h01 * h01 : 0.f) + (v1r ? h11 * h11 : 0.f);
            #pragma unroll
            for (int off = 16; off >= 4; off >>= 1) {
                sA += __shfl_down_sync(0xffffffffu, sA, off);
                sB += __shfl_down_sync(0xffffffffu, sB, off);
                qA += __shfl_down_sync(0xffffffffu, qA, off);
                qB += __shfl_down_sync(0xffffffffu, qB, off);
            }
            if (lane < 4) {
                *(float2*)&redS[warp_m * 128 + col] = make_float2(sA, sB);
                *(float2*)&redQ[warp_m * 128 + col] = make_float2(qA, qB);
            }
        }
        __syncthreads();
        if (tid < 128) {
            float s = redS[tid] + redS[128 + tid] + redS[256 + tid] + redS[384 + tid];
            float q = redQ[tid] + redQ[128 + tid] + redQ[256 + tid] + redQ[384 + tid];
            atomicAdd(&g_sum[tid], s);
            atomicAdd(&g_sumsq[tid], q);
        }
    }
}

// ---------------- layer-3 mma GEMM (persistent tiles): y = relu(bn2(h2))@W3 * n_out ----
__global__ __launch_bounds__(256)
void mma_gemm64_kernel(const float* __restrict__ A,
                       const float* __restrict__ W,
                       float* __restrict__ out) {
    extern __shared__ float smem[];
    float*  As_f = smem;                    // 64*132
    float4* As4  = (float4*)smem;
    float*  Wt   = smem + 64 * 132;         // 64*133 (transposed W3)

    int tid = threadIdx.x;
    int lane = tid & 31;
    int wid = tid >> 5;
    int warp_m = wid & 3;
    int wn = wid >> 2;
    int qr = lane >> 2;
    int rr = lane & 3;
    int m0 = warp_m * 16 + qr;

    // stage W3 transposed ONCE: Wt[n*133 + k] = W[k*64 + n]
    for (int i = tid; i < 128 * 64; i += 256) {
        int k = i >> 6, n = i & 63;
        Wt[n * 133 + k] = W[i];
    }

    for (int tile = blockIdx.x; tile < N_TILES; tile += gridDim.x) {
        int rowBase = tile * 64;
        __syncthreads();

        #pragma unroll
        for (int i = 0; i < 8; i++) {
            int slot = tid + i * 256;
            int lrow = slot >> 5;
            int kk = slot & 31;
            int grow = rowBase + lrow;
            float4 v = make_float4(0.f, 0.f, 0.f, 0.f);
            if (grow < N_NODES) {
                v = ((const float4*)A)[(size_t)grow * 32 + kk];
                float4 a4 = ((const float4*)g_bna)[kk];
                float4 b4 = ((const float4*)g_bnb)[kk];
                v = bn_relu4(v, a4, b4);
            }
            As4[lrow * 33 + kk] = v;
        }
        __syncthreads();

        float c[4][4];
        #pragma unroll
        for (int nt = 0; nt < 4; nt++)
            #pragma unroll
            for (int q = 0; q < 4; q++) c[nt][q] = 0.f;

        #pragma unroll 2
        for (int ks = 0; ks < 16; ks++) {
            int k0 = ks * 8;
            float av0 = As_f[m0 * 132 + k0 + rr];
            float av1 = As_f[(m0 + 8) * 132 + k0 + rr];
            float av2 = As_f[m0 * 132 + k0 + 4 + rr];
            float av3 = As_f[(m0 + 8) * 132 + k0 + 4 + rr];
            uint32_t ah[4], al[4];
            ah[0] = f2tf(av0); al[0] = f2tf(av0 - __uint_as_float(ah[0]));
            ah[1] = f2tf(av1); al[1] = f2tf(av1 - __uint_as_float(ah[1]));
            ah[2] = f2tf(av2); al[2] = f2tf(av2 - __uint_as_float(ah[2]));
            ah[3] = f2tf(av3); al[3] = f2tf(av3 - __uint_as_float(ah[3]));
            #pragma unroll
            for (int nt = 0; nt < 4; nt++) {
                int nb = (wn * 32 + nt * 8 + qr) * 133 + k0 + rr;
                float b0 = Wt[nb];
                float b1 = Wt[nb + 4];
                uint32_t bh0 = f2tf(b0);
                uint32_t bh1 = f2tf(b1);
                uint32_t bl0 = __float_as_uint(b0 - __uint_as_float(bh0));
                uint32_t bl1 = __float_as_uint(b1 - __uint_as_float(bh1));
                mma_tf32(c[nt], ah, bh0, bh1);
                mma_tf32(c[nt], al, bh0, bh1);
                mma_tf32(c[nt], ah, bl0, bl1);
            }
        }

        int g0 = rowBase + m0;
        int g1 = g0 + 8;
        float s0 = (g0 < N_NODES) ? g_nout[g0] : 0.f;
        float s1 = (g1 < N_NODES) ? g_nout[g1] : 0.f;
        #pragma unroll
        for (int nt = 0; nt < 4; nt++) {
            int col = wn * 32 + nt * 8 + 2 * rr;
            if (g0 < N_NODES)
                *(float2*)&out[(size_t)g0 * 64 + col] =
                    make_float2(c[nt][0] * s0, c[nt][1] * s0);
            if (g1 < N_NODES)
                *(float2*)&out[(size_t)g1 * 64 + col] =
                    make_float2(c[nt][2] * s1, c[nt][3] * s1);
        }
        __syncthreads();
    }
}

// ---------------- BN finalize ----------------
__global__ void bn_finalize_kernel(const float* __restrict__ gamma,
                                   const float* __restrict__ beta) {
    int t = threadIdx.x;
    if (t < F_HID) {
        float mean = g_sum[t] / (float)N_NODES;
        float var = g_sumsq[t] / (float)N_NODES - mean * mean;
        float a = gamma[t] * rsqrtf(var + BN_EPS);
        g_bna[t] = a;
        g_bnb[t] = fmaf(-mean, a, beta[t]);
        g_sum[t] = 0.f;
        g_sumsq[t] = 0.f;
    }
}

// ---------------- final CSR gather (64 feats), dual-node per warp ----------------
__global__ void gather64_kernel(const float* __restrict__ y,
                                const float* __restrict__ b3,
                                float* __restrict__ out) {
    int w = (blockIdx.x * blockDim.x + threadIdx.x) >> 5;
    int lane = threadIdx.x & 31;
    int nA = 2 * w, nB = 2 * w + 1;
    if (nA >= N_NODES) return;
    const float2* y2 = (const float2*)y;

    int jA = g_row_ptr[nA], eA = g_row_ptr[nA + 1];
    int jB = 0, eB = 0;
    if (nB < N_NODES) { jB = g_row_ptr[nB]; eB = g_row_ptr[nB + 1]; }
    float2 accA = make_float2(0.f, 0.f);
    float2 accB = make_float2(0.f, 0.f);

    while (jA + 4 <= eA && jB + 4 <= eB) {
        int sA[4], sB[4];
        #pragma unroll
        for (int u = 0; u < 4; u++) { sA[u] = g_csr_pack[jA + u].x; sB[u] = g_csr_pack[jB + u].x; }
        float2 vA[4], vB[4];
        #pragma unroll
        for (int u = 0; u < 4; u++) {
            vA[u] = y2[(size_t)sA[u] * 32 + lane];
            vB[u] = y2[(size_t)sB[u] * 32 + lane];
        }
        #pragma unroll
        for (int u = 0; u < 4; u++) {
            accA.x += vA[u].x; accA.y += vA[u].y;
            accB.x += vB[u].x; accB.y += vB[u].y;
        }
        jA += 4; jB += 4;
    }
    for (; jA < eA; jA++) {
        float2 v = y2[(size_t)g_csr_pack[jA].x * 32 + lane];
        accA.x += v.x; accA.y += v.y;
    }
    for (; jB < eB; jB++) {
        float2 v = y2[(size_t)g_csr_pack[jB].x * 32 + lane];
        accB.x += v.x; accB.y += v.y;
    }

    float2 b = ((const float2*)b3)[lane];
    float niA = g_nin[nA];
    ((float2*)out)[(size_t)nA * 32 + lane] =
        make_float2(fmaf(accA.x, niA, b.x), fmaf(accA.y, niA, b.y));
    if (nB < N_NODES) {
        float niB = g_nin[nB];
        ((float2*)out)[(size_t)nB * 32 + lane] =
            make_float2(fmaf(accB.x, niB, b.x), fmaf(accB.y, niB, b.y));
    }
}

// ---------------- host launcher ----------------
extern "C" void kernel_launch(void* const* d_in, const int* in_sizes, int n_in,
                              void* d_out, int out_size) {
    const float* features = (const float*)d_in[0];
    const int*   srcbuf   = (const int*)d_in[1];
    const int*   dstbuf   = (const int*)d_in[2];
    const float* W1  = (const float*)d_in[3];
    const float* b1  = (const float*)d_in[4];
    const float* ga1 = (const float*)d_in[5];
    const float* be1 = (const float*)d_in[6];
    const float* W2  = (const float*)d_in[7];
    const float* b2  = (const float*)d_in[8];
    const float* ga2 = (const float*)d_in[9];
    const float* be2 = (const float*)d_in[10];
    const float* W3  = (const float*)d_in[11];
    const float* b3  = (const float*)d_in[12];
    float* out = (float*)d_out;

    void* p;
    cudaGetSymbolAddress(&p, g_h1);
    float* p_h1 = (float*)p;
    cudaGetSymbolAddress(&p, g_h2);
    float* p_h2 = (float*)p;
    void *p_do, *p_di, *p_sum, *p_sq;
    cudaGetSymbolAddress(&p_do, g_deg_out);
    cudaGetSymbolAddress(&p_di, g_deg_in);
    cudaGetSymbolAddress(&p_sum, g_sum);
    cudaGetSymbolAddress(&p_sq, g_sumsq);

    constexpr int SM_CONV = (64 * 132 + 128 * 133 + 1024) * 4;   // 105984
    constexpr int SM_G64  = (64 * 132 + 64 * 133) * 4;           // 67840

    cudaFuncSetAttribute(fused_conv_kernel<1>,
                         cudaFuncAttributeMaxDynamicSharedMemorySize, SM_CONV);
    cudaFuncSetAttribute(fused_conv_kernel<2>,
                         cudaFuncAttributeMaxDynamicSharedMemorySize, SM_CONV);
    cudaFuncSetAttribute(mma_gemm64_kernel,
                         cudaFuncAttributeMaxDynamicSharedMemorySize, SM_G64);

    int eblk = (N_EDGES + 255) / 256;

    // graph preprocessing
    cudaMemsetAsync(p_do, 0, N_NODES * sizeof(int));
    cudaMemsetAsync(p_di, 0, N_NODES * sizeof(int));
    cudaMemsetAsync(p_sum, 0, F_HID * sizeof(float));
    cudaMemsetAsync(p_sq, 0, F_HID * sizeof(float));
    detect_kernel<<<1, 32>>>(srcbuf);
    degree_kernel<<<eblk, 256>>>(srcbuf, dstbuf);
    scanA_kernel<<<SCAN_BLOCKS, 1024>>>();
    scanB_kernel<<<SCAN_BLOCKS, 1024>>>();
    fill_csr_kernel<<<eblk, 256>>>(srcbuf, dstbuf);

    // ---- layer 1 ----
    fused_conv_kernel<1><<<PERSIST_BLOCKS, 256, SM_CONV>>>(features, W1, b1, p_h1);
    bn_finalize_kernel<<<1, 128>>>(ga1, be1);

    // ---- layer 2 ----
    fused_conv_kernel<2><<<PERSIST_BLOCKS, 256, SM_CONV>>>(p_h1, W2, b2, p_h2);
    bn_finalize_kernel<<<1, 128>>>(ga2, be2);

    // ---- layer 3: GEMM first (aggregation commutes with W3), then CSR gather ----
    mma_gemm64_kernel<<<PERSIST_BLOCKS, 256, SM_G64>>>(p_h2, W3, p_h1);
    gather64_kernel<<<(N_NODES / 2 + 7) / 8, 256>>>(p_h1, b3, out);
}